// round 3
// baseline (speedup 1.0000x reference)
#include <cuda_runtime.h>
#include <stdint.h>

#define NBATCH 8
#define NCLS   80
#define ROWS   17328      // A*HW = 3*5776
#define TOPK   200
#define CAP    1024       // shared candidate buffer capacity (fallback path)
#define CAP_G  768        // global per-(b,c) candidate list capacity
#define KW     7          // ceil(200/32) words for keep/suppress bitmasks
#define NPIV   6
#define NBC    (NBATCH * NCLS)

// Global scratch (static: no allocation)
__device__ unsigned long long g_cand[NBC * CAP_G];   // ~3.9 MB
__device__ int g_ccnt[NBC];
__device__ int g_pivcnt[NBC * NPIV];

__device__ __forceinline__ unsigned long long make_key(float v, int idx) {
    return ((unsigned long long)__float_as_uint(v) << 32) | (unsigned int)(~idx);
}

// ---------------------------------------------------------------------------
// Kernel 0: zero the counters
// ---------------------------------------------------------------------------
__global__ void zero_kernel() {
    int t = blockIdx.x * 256 + threadIdx.x;
    if (t < NBC) g_ccnt[t] = 0;
    if (t < NBC * NPIV) g_pivcnt[t] = 0;
}

// ---------------------------------------------------------------------------
// Kernel 1: single coalesced pass over scores in native (B, ROWS, C) layout.
// blockDim = 320 = 4*80, so each thread's class is fixed (tid % 80).
// Accumulates 6 pivot counters per (b, class) and pushes >0.98 candidates
// into per-(b,c) global lists.
// ---------------------------------------------------------------------------
__global__ void __launch_bounds__(320) scatter_kernel(const float* __restrict__ scores) {
    __shared__ int s_piv[NCLS * NPIV];
    const int b = blockIdx.y;
    const int chunk = blockIdx.x;
    const int t = threadIdx.x;
    if (t < NCLS * NPIV) s_piv[t] = 0;
    __syncthreads();

    const int cls  = t % NCLS;
    const int row0 = chunk * 256 + t / NCLS;
    const int bc   = b * NCLS + cls;
    const float* base = scores + (size_t)b * ROWS * NCLS;

    int c0 = 0, c1 = 0, c2 = 0, c3 = 0, c4 = 0, c5 = 0;
    #pragma unroll 4
    for (int it = 0; it < 64; it++) {
        int row = row0 + it * 4;
        if (row < ROWS) {
            float v = base[(size_t)row * NCLS + cls];
            c0 += (v > 0.98f); c1 += (v > 0.96f); c2 += (v > 0.92f);
            c3 += (v > 0.84f); c4 += (v > 0.68f); c5 += (v > 0.50f);
            if (v > 0.98f) {
                int pos = atomicAdd(&g_ccnt[bc], 1);
                if (pos < CAP_G) g_cand[(size_t)bc * CAP_G + pos] = make_key(v, row);
            }
        }
    }
    atomicAdd(&s_piv[cls * NPIV + 0], c0);
    atomicAdd(&s_piv[cls * NPIV + 1], c1);
    atomicAdd(&s_piv[cls * NPIV + 2], c2);
    atomicAdd(&s_piv[cls * NPIV + 3], c3);
    atomicAdd(&s_piv[cls * NPIV + 4], c4);
    atomicAdd(&s_piv[cls * NPIV + 5], c5);
    __syncthreads();
    if (t < NCLS * NPIV && s_piv[t] != 0)
        atomicAdd(&g_pivcnt[b * NCLS * NPIV + t], s_piv[t]);
}

// ---------------------------------------------------------------------------
// Kernel 2: one CTA per (batch, class). Sort candidates + greedy NMS.
// ---------------------------------------------------------------------------
__global__ void __launch_bounds__(256) nms_kernel(const float* __restrict__ boxes,
                                                  const float* __restrict__ scores,
                                                  float* __restrict__ out) {
    const int tid = threadIdx.x;
    const int bc  = blockIdx.x;            // b*80 + c
    const int b   = bc / NCLS;
    const int c   = bc % NCLS;

    __shared__ unsigned long long keys[CAP];
    __shared__ float4 s_box4[TOPK];
    __shared__ float s_area[TOPK], s_sc[TOPK];
    __shared__ unsigned int sup[TOPK * KW];
    __shared__ unsigned int s_keepw[KW];
    __shared__ int s_num;

    const int n05    = g_pivcnt[bc * NPIV + (NPIV - 1)];
    const int cnt098 = g_ccnt[bc];
    const int target = (n05 < TOPK) ? n05 : TOPK;

    int cnt;
    if (cnt098 >= target && cnt098 <= CAP_G) {
        // ---- Main path: load the prebuilt candidate list
        cnt = cnt098;
        const unsigned long long* src = g_cand + (size_t)bc * CAP_G;
        for (int k = tid; k < cnt; k += 256) keys[k] = src[k];
    } else {
        // ---- Fallback (statistically never taken): strided rescan with pivot ladder
        if (tid == 0) s_num = 0;
        __syncthreads();
        const float pvs[NPIV] = {0.98f, 0.96f, 0.92f, 0.84f, 0.68f, 0.50f};
        float pivot = 0.50f;
        #pragma unroll
        for (int p = NPIV - 1; p >= 0; p--)
            if (g_pivcnt[bc * NPIV + p] >= target) pivot = pvs[p];
        const float* col = scores + (size_t)b * ROWS * NCLS + c;
        for (int i = tid; i < ROWS; i += 256) {
            float v = col[(size_t)i * NCLS];
            if (v > pivot) {
                int pos = atomicAdd(&s_num, 1);
                if (pos < CAP) keys[pos] = make_key(v, i);
            }
        }
        __syncthreads();
        cnt = s_num; if (cnt > CAP) cnt = CAP;
    }
    __syncthreads();

    // ---- Pad to power of two and bitonic sort descending
    int P = 256; while (P < cnt) P <<= 1;
    for (int i = cnt + tid; i < P; i += 256) keys[i] = 0ull;
    __syncthreads();

    for (int k = 2; k <= P; k <<= 1) {
        for (int j = k >> 1; j > 0; j >>= 1) {
            for (int i = tid; i < P; i += 256) {
                int l = i ^ j;
                if (l > i) {
                    unsigned long long a = keys[i], d = keys[l];
                    bool sw = ((i & k) == 0) ? (a < d) : (a > d);
                    if (sw) { keys[i] = d; keys[l] = a; }
                }
            }
            __syncthreads();
        }
    }

    const int n_top = (cnt < TOPK) ? cnt : TOPK;

    // ---- Gather boxes for the top-200
    for (int k = tid; k < TOPK; k += 256) {
        if (k < n_top) {
            unsigned long long key = keys[k];
            int idx = (int)(~(unsigned int)(key & 0xffffffffull));
            float4 bb = ((const float4*)boxes)[(size_t)b * ROWS + idx];
            s_box4[k] = bb;
            s_area[k] = (bb.z - bb.x) * (bb.w - bb.y);
            s_sc[k]   = __uint_as_float((unsigned int)(key >> 32));
        } else {
            s_box4[k] = make_float4(0.f, 0.f, 0.f, 0.f);
            s_area[k] = 0.f; s_sc[k] = 0.f;
        }
    }
    __syncthreads();

    // ---- Suppression bitmask: thread i owns row i; inner j is a shared-mem
    //      broadcast (conflict-free). sup[i][w] bit jj: iou(i, w*32+jj) > 0.5, j > i.
    const int i = tid;
    if (i < n_top) {
        const float4 bi = s_box4[i];
        const float  ai = s_area[i];
        const int    w0 = i >> 5;
        #pragma unroll
        for (int w = 0; w < KW; w++) {
            unsigned int m = 0;
            if (w >= w0) {
                const int jend = (n_top - w * 32 < 32) ? (n_top - w * 32) : 32;
                #pragma unroll 8
                for (int jj = 0; jj < 32; jj++) {
                    if (jj >= jend) break;
                    int j = w * 32 + jj;
                    if (j > i) {
                        float4 bj = s_box4[j];
                        float xx1 = fmaxf(bi.x, bj.x);
                        float yy1 = fmaxf(bi.y, bj.y);
                        float xx2 = fminf(bi.z, bj.z);
                        float yy2 = fminf(bi.w, bj.w);
                        float inter = fmaxf(0.f, xx2 - xx1) * fmaxf(0.f, yy2 - yy1);
                        if (inter > 0.f) {
                            float un = (ai + s_area[j]) - inter;
                            if (inter / un > 0.5f) m |= (1u << jj);
                        }
                    }
                }
            }
            sup[i * KW + w] = m;
        }
    }
    __syncthreads();

    // ---- Serial greedy (thread 0, rem[] fully in registers via unrolled outer)
    if (tid == 0) {
        unsigned int rem[KW];
        #pragma unroll
        for (int w = 0; w < KW; w++) rem[w] = 0u;
        #pragma unroll
        for (int w0 = 0; w0 < KW; w0++) {
            int ibase = w0 * 32;
            for (int ii = 0; ii < 32; ii++) {
                int idx = ibase + ii;
                if (idx >= n_top) break;
                if (((rem[w0] >> ii) & 1u) == 0u) {
                    #pragma unroll
                    for (int w = 0; w < KW; w++) rem[w] |= sup[idx * KW + w];
                }
            }
        }
        #pragma unroll
        for (int w = 0; w < KW; w++) s_keepw[w] = ~rem[w];
    }
    __syncthreads();

    // ---- Write output: (b, c, k, 6) = [x1,y1,x2,y2,score,class] or zeros
    float* o = out + (size_t)bc * (TOPK * 6);
    const float cls = (float)c;
    for (int t = tid; t < TOPK * 6; t += 256) {
        int k = t / 6, f = t % 6;
        bool kp = (k < n_top) && (((s_keepw[k >> 5] >> (k & 31)) & 1u) != 0u);
        float v = 0.f;
        if (kp) {
            switch (f) {
                case 0: v = s_box4[k].x; break;
                case 1: v = s_box4[k].y; break;
                case 2: v = s_box4[k].z; break;
                case 3: v = s_box4[k].w; break;
                case 4: v = s_sc[k]; break;
                default: v = cls;   break;
            }
        }
        o[t] = v;
    }
}

// ---------------------------------------------------------------------------
extern "C" void kernel_launch(void* const* d_in, const int* in_sizes, int n_in,
                              void* d_out, int out_size) {
    const float* boxes  = (const float*)d_in[0];
    const float* scores = (const float*)d_in[1];
    if (n_in >= 2 && in_sizes[0] > in_sizes[1]) {  // scores is the bigger tensor
        boxes  = (const float*)d_in[1];
        scores = (const float*)d_in[0];
    }
    float* out = (float*)d_out;

    zero_kernel<<<(NBC * NPIV + 255) / 256, 256>>>();

    dim3 sgrid((ROWS + 255) / 256, NBATCH);
    scatter_kernel<<<sgrid, 320>>>(scores);

    nms_kernel<<<NBC, 256>>>(boxes, scores, out);
}

// round 4
// speedup vs baseline: 1.0872x; 1.0872x over previous
#include <cuda_runtime.h>
#include <stdint.h>

#define NBATCH 8
#define NCLS   80
#define ROWS   17328                  // A*HW = 3*5776
#define PERB   (ROWS * NCLS)          // 1386240 elements per batch
#define NTOT   (NBATCH * PERB)        // 11089920
#define N4     (NTOT / 4)             // 2772480 float4s
#define TOPK   200
#define CAP    1024                   // sort buffer capacity
#define CAP_G  768                    // global per-(b,c) candidate list capacity
#define KW     7                      // ceil(200/32) words for bitmasks
#define NBC    (NBATCH * NCLS)
#define NFINE  5
#define NLAD   11
#define SCAT_BLK ((N4 + 2047) / 2048) // 1354

// Global scratch (static, zero-initialized at module load)
__device__ unsigned long long g_cand[NBC * CAP_G];   // ~3.9 MB
__device__ int g_ccnt[NBC];                          // reset by nms each run

__device__ __forceinline__ unsigned long long make_key(float v, int idx) {
    return ((unsigned long long)__float_as_uint(v) << 32) | (unsigned int)(~idx);
}

// ---------------------------------------------------------------------------
// Kernel 1: flat coalesced scan. ~2 instructions per element.
// Pushes >0.98 candidates into per-(b,c) global lists; the atomic IS the count.
// ---------------------------------------------------------------------------
__global__ void __launch_bounds__(256) scatter_kernel(const float4* __restrict__ s4) {
    const int base = blockIdx.x * 2048 + threadIdx.x;
    #pragma unroll
    for (int k = 0; k < 8; k++) {
        const int i4 = base + k * 256;
        if (i4 < N4) {
            float4 v = s4[i4];
            if (fmaxf(fmaxf(v.x, v.y), fmaxf(v.z, v.w)) > 0.98f) {
                float a[4] = {v.x, v.y, v.z, v.w};
                #pragma unroll
                for (int u = 0; u < 4; u++) {
                    if (a[u] > 0.98f) {
                        int e   = i4 * 4 + u;
                        int b   = e / PERB;
                        int rem = e - b * PERB;
                        int row = rem / NCLS;
                        int cls = rem - row * NCLS;
                        int bc  = b * NCLS + cls;
                        int pos = atomicAdd(&g_ccnt[bc], 1);
                        if (pos < CAP_G) g_cand[bc * CAP_G + pos] = make_key(a[u], row);
                    }
                }
            }
        }
    }
}

// ---------------------------------------------------------------------------
// Kernel 2: one CTA per (batch, class). Refine pivot + sort + greedy NMS.
// ---------------------------------------------------------------------------
__global__ void __launch_bounds__(256) nms_kernel(const float* __restrict__ boxes,
                                                  const float* __restrict__ scores,
                                                  float* __restrict__ out) {
    const int tid  = threadIdx.x;
    const int lane = tid & 31;
    const int wid  = tid >> 5;
    const int bc   = blockIdx.x;
    const int b    = bc / NCLS;
    const int c    = bc % NCLS;

    __shared__ unsigned long long keys[CAP];
    __shared__ float4 s_box4[TOPK];
    __shared__ float s_area[TOPK], s_sc[TOPK];
    __shared__ unsigned int sup[TOPK * KW];
    __shared__ unsigned int s_keepw[KW];
    __shared__ int s_num, s_fcnt[NFINE], s_pcnt[NLAD];

    const int cnt098 = g_ccnt[bc];

    if (tid < NFINE) s_fcnt[tid] = 0;
    if (tid == 0) s_num = 0;
    __syncthreads();

    int cnt;
    if (cnt098 >= TOPK && cnt098 <= CAP_G) {
        // ---- Fast path: list is complete and holds >= 200 candidates.
        unsigned long long kreg[3];
        const unsigned long long* src = g_cand + (size_t)bc * CAP_G;
        #pragma unroll
        for (int r = 0; r < 3; r++) {
            int k = tid + r * 256;
            kreg[r] = (k < cnt098) ? src[k] : 0ull;
        }
        // Fine-level histogram on the candidate scores (registers only)
        const float FL[NFINE] = {0.9950f, 0.9925f, 0.9900f, 0.9875f, 0.9850f};
        int lc[NFINE] = {0, 0, 0, 0, 0};
        #pragma unroll
        for (int r = 0; r < 3; r++) {
            float sc = __uint_as_float((unsigned int)(kreg[r] >> 32));
            #pragma unroll
            for (int f = 0; f < NFINE; f++) lc[f] += (sc > FL[f]);
        }
        #pragma unroll
        for (int f = 0; f < NFINE; f++) {
            int ws = __reduce_add_sync(0xffffffffu, lc[f]);
            if (lane == 0 && ws) atomicAdd(&s_fcnt[f], ws);
        }
        __syncthreads();
        // Finest level still holding >= 200 candidates
        float pivot = 0.98f;
        #pragma unroll
        for (int f = NFINE - 1; f >= 0; f--)
            if (s_fcnt[f] >= TOPK) pivot = FL[f];
        // Compact selected keys into the sort buffer
        #pragma unroll
        for (int r = 0; r < 3; r++) {
            float sc = __uint_as_float((unsigned int)(kreg[r] >> 32));
            if (sc > pivot) {
                int pos = atomicAdd(&s_num, 1);
                keys[pos] = kreg[r];
            }
        }
        __syncthreads();
        cnt = s_num;
    } else {
        // ---- Fallback (statistically never): full strided rescan with ladder.
        if (tid < NLAD) s_pcnt[tid] = 0;
        __syncthreads();
        const float PL[NLAD] = {0.9950f, 0.9925f, 0.9900f, 0.9875f, 0.9850f,
                                0.98f, 0.96f, 0.92f, 0.84f, 0.68f, 0.50f};
        const float* col = scores + (size_t)b * PERB + c;
        int lc[NLAD];
        #pragma unroll
        for (int l = 0; l < NLAD; l++) lc[l] = 0;
        for (int i = tid; i < ROWS; i += 256) {
            float v = col[(size_t)i * NCLS];
            #pragma unroll
            for (int l = 0; l < NLAD; l++) lc[l] += (v > PL[l]);
        }
        #pragma unroll
        for (int l = 0; l < NLAD; l++) {
            int ws = __reduce_add_sync(0xffffffffu, lc[l]);
            if (lane == 0 && ws) atomicAdd(&s_pcnt[l], ws);
        }
        __syncthreads();
        const int n05 = s_pcnt[NLAD - 1];
        const int target = (n05 < TOPK) ? n05 : TOPK;
        float pivot = 0.50f;
        #pragma unroll
        for (int l = NLAD - 1; l >= 0; l--)
            if (s_pcnt[l] >= target) pivot = PL[l];
        for (int i = tid; i < ROWS; i += 256) {
            float v = col[(size_t)i * NCLS];
            if (v > pivot) {
                int pos = atomicAdd(&s_num, 1);
                if (pos < CAP) keys[pos] = make_key(v, i);
            }
        }
        __syncthreads();
        cnt = s_num; if (cnt > CAP) cnt = CAP;
    }

    // ---- Pad to power of two, bitonic sort descending (64-bit keys)
    int P = 256; while (P < cnt) P <<= 1;
    for (int i = cnt + tid; i < P; i += 256) keys[i] = 0ull;
    __syncthreads();
    for (int k = 2; k <= P; k <<= 1) {
        for (int j = k >> 1; j > 0; j >>= 1) {
            for (int i = tid; i < P; i += 256) {
                int l = i ^ j;
                if (l > i) {
                    unsigned long long a = keys[i], d = keys[l];
                    bool sw = ((i & k) == 0) ? (a < d) : (a > d);
                    if (sw) { keys[i] = d; keys[l] = a; }
                }
            }
            __syncthreads();
        }
    }

    const int n_top = (cnt < TOPK) ? cnt : TOPK;

    // ---- Gather boxes for the top-200
    for (int k = tid; k < TOPK; k += 256) {
        if (k < n_top) {
            unsigned long long key = keys[k];
            int idx = (int)(~(unsigned int)(key & 0xffffffffull));
            float4 bb = ((const float4*)boxes)[(size_t)b * ROWS + idx];
            s_box4[k] = bb;
            s_area[k] = (bb.z - bb.x) * (bb.w - bb.y);
            s_sc[k]   = __uint_as_float((unsigned int)(key >> 32));
        } else {
            s_box4[k] = make_float4(0.f, 0.f, 0.f, 0.f);
            s_area[k] = 0.f; s_sc[k] = 0.f;
        }
    }
    __syncthreads();

    // ---- Suppression bitmask: one warp per row, lane jj = bit jj of word w.
    //      Rows round-robin over warps -> balanced triangle. Ballot forms word.
    for (int r = wid; r < n_top; r += 8) {
        const float4 bi = s_box4[r];
        const float  ai = s_area[r];
        const int    w0 = r >> 5;
        for (int w = w0; w < KW; w++) {
            int j = w * 32 + lane;
            bool hit = false;
            if (j > r && j < n_top) {
                float4 bj = s_box4[j];
                float xx1 = fmaxf(bi.x, bj.x);
                float yy1 = fmaxf(bi.y, bj.y);
                float xx2 = fminf(bi.z, bj.z);
                float yy2 = fminf(bi.w, bj.w);
                float inter = fmaxf(0.f, xx2 - xx1) * fmaxf(0.f, yy2 - yy1);
                if (inter > 0.f) {
                    float un = (ai + s_area[j]) - inter;
                    hit = (inter / un) > 0.5f;
                }
            }
            unsigned int m = __ballot_sync(0xffffffffu, hit);
            if (lane == 0) sup[r * KW + w] = m;
        }
    }
    __syncthreads();

    // ---- Serial greedy on thread 0 (rem[] in registers; only words w >= w0
    //      can be touched by rows in block w0, so OR range is pruned).
    if (tid == 0) {
        unsigned int rem[KW];
        #pragma unroll
        for (int w = 0; w < KW; w++) rem[w] = 0u;
        #pragma unroll
        for (int w0 = 0; w0 < KW; w0++) {
            for (int ii = 0; ii < 32; ii++) {
                int idx = w0 * 32 + ii;
                if (idx >= n_top) break;
                if (((rem[w0] >> ii) & 1u) == 0u) {
                    #pragma unroll
                    for (int w = 0; w < KW; w++)
                        if (w >= w0) rem[w] |= sup[idx * KW + w];
                }
            }
        }
        #pragma unroll
        for (int w = 0; w < KW; w++) s_keepw[w] = ~rem[w];
        g_ccnt[bc] = 0;   // self-clean for next graph replay
    }
    __syncthreads();

    // ---- Write output: (b, c, k, 6) = [x1,y1,x2,y2,score,class] or zeros
    float* o = out + (size_t)bc * (TOPK * 6);
    const float cls = (float)c;
    for (int t = tid; t < TOPK * 6; t += 256) {
        int k = t / 6, f = t % 6;
        bool kp = (k < n_top) && (((s_keepw[k >> 5] >> (k & 31)) & 1u) != 0u);
        float v = 0.f;
        if (kp) {
            switch (f) {
                case 0: v = s_box4[k].x; break;
                case 1: v = s_box4[k].y; break;
                case 2: v = s_box4[k].z; break;
                case 3: v = s_box4[k].w; break;
                case 4: v = s_sc[k]; break;
                default: v = cls;   break;
            }
        }
        o[t] = v;
    }
}

// ---------------------------------------------------------------------------
extern "C" void kernel_launch(void* const* d_in, const int* in_sizes, int n_in,
                              void* d_out, int out_size) {
    const float* boxes  = (const float*)d_in[0];
    const float* scores = (const float*)d_in[1];
    if (n_in >= 2 && in_sizes[0] > in_sizes[1]) {  // scores is the bigger tensor
        boxes  = (const float*)d_in[1];
        scores = (const float*)d_in[0];
    }
    float* out = (float*)d_out;

    scatter_kernel<<<SCAT_BLK, 256>>>((const float4*)scores);
    nms_kernel<<<NBC, 256>>>(boxes, scores, out);
}

// round 5
// speedup vs baseline: 1.2392x; 1.1398x over previous
#include <cuda_runtime.h>
#include <stdint.h>

#define NBATCH 8
#define NCLS   80
#define ROWS   17328                  // A*HW = 3*5776
#define PERB   (ROWS * NCLS)          // 1386240 elements per batch
#define NTOT   (NBATCH * PERB)        // 11089920
#define N4     (NTOT / 4)             // 2772480 float4s
#define TOPK   200
#define CAP    1024                   // sort buffer capacity (fallback)
#define CAP_G  768                    // global per-(b,c) candidate list capacity
#define KW     7                      // words actually used for bitmasks
#define KW8    8                      // padded stride (uint4 x2 per row)
#define NBC    (NBATCH * NCLS)
#define NFINE  9
#define NLAD   11
#define SCAT_E   10
#define SCAT_BLK 1083                 // 1083*256*10 = 2772480 = N4 exactly

// Global scratch (static, zero-initialized at module load)
__device__ unsigned long long g_cand[NBC * CAP_G];   // ~3.9 MB
__device__ int g_ccnt[NBC];                          // reset by nms each run

__device__ __forceinline__ unsigned long long make_key(float v, int idx) {
    return ((unsigned long long)__float_as_uint(v) << 32) | (unsigned int)(~idx);
}

// ---------------------------------------------------------------------------
// Kernel 1: flat coalesced scan, exact-fit grid (no bounds checks).
// Pushes >0.98 candidates into per-(b,c) global lists; the atomic IS the count.
// ---------------------------------------------------------------------------
__global__ void __launch_bounds__(256) scatter_kernel(const float4* __restrict__ s4) {
    const int base = blockIdx.x * (SCAT_E * 256) + threadIdx.x;
    #pragma unroll
    for (int k = 0; k < SCAT_E; k++) {
        const int i4 = base + k * 256;
        float4 v = __ldcs(&s4[i4]);
        if (fmaxf(fmaxf(v.x, v.y), fmaxf(v.z, v.w)) > 0.98f) {
            float a[4] = {v.x, v.y, v.z, v.w};
            #pragma unroll
            for (int u = 0; u < 4; u++) {
                if (a[u] > 0.98f) {
                    int e   = i4 * 4 + u;
                    int b   = e / PERB;
                    int rem = e - b * PERB;
                    int row = rem / NCLS;
                    int cls = rem - row * NCLS;
                    int bc  = b * NCLS + cls;
                    int pos = atomicAdd(&g_ccnt[bc], 1);
                    if (pos < CAP_G) g_cand[bc * CAP_G + pos] = make_key(a[u], row);
                }
            }
        }
    }
}

// ---------------------------------------------------------------------------
// Kernel 2: one CTA per (batch, class). Refine pivot + sort + greedy NMS.
// ---------------------------------------------------------------------------
__global__ void __launch_bounds__(256) nms_kernel(const float* __restrict__ boxes,
                                                  const float* __restrict__ scores,
                                                  float* __restrict__ out) {
    const int tid  = threadIdx.x;
    const int lane = tid & 31;
    const int wid  = tid >> 5;
    const int bc   = blockIdx.x;
    const int b    = bc / NCLS;
    const int c    = bc % NCLS;

    __shared__ unsigned long long keys[CAP];
    __shared__ float4 s_box4[TOPK];
    __shared__ float s_area[TOPK], s_sc[TOPK];
    __shared__ unsigned int sup[(TOPK + 1) * KW8];
    __shared__ unsigned int s_keepw[KW];
    __shared__ int s_num, s_fcnt[NFINE], s_pcnt[NLAD];

    const int cnt098 = g_ccnt[bc];

    if (tid < NFINE) s_fcnt[tid] = 0;
    if (tid == 0) s_num = 0;
    __syncthreads();

    int cnt;
    if (cnt098 >= TOPK && cnt098 <= CAP_G) {
        // ---- Fast path: list is complete and holds >= 200 candidates.
        unsigned long long kreg[3];
        const unsigned long long* src = g_cand + (size_t)bc * CAP_G;
        #pragma unroll
        for (int r = 0; r < 3; r++) {
            int k = tid + r * 256;
            kreg[r] = (k < cnt098) ? src[k] : 0ull;
        }
        // Fine-level histogram on the candidate scores (registers only)
        const float FL[NFINE] = {0.99500f, 0.99375f, 0.99250f, 0.99125f, 0.99000f,
                                 0.98875f, 0.98750f, 0.98625f, 0.98500f};
        int lc[NFINE];
        #pragma unroll
        for (int f = 0; f < NFINE; f++) lc[f] = 0;
        #pragma unroll
        for (int r = 0; r < 3; r++) {
            float sc = __uint_as_float((unsigned int)(kreg[r] >> 32));
            #pragma unroll
            for (int f = 0; f < NFINE; f++) lc[f] += (sc > FL[f]);
        }
        #pragma unroll
        for (int f = 0; f < NFINE; f++) {
            int ws = __reduce_add_sync(0xffffffffu, lc[f]);
            if (lane == 0 && ws) atomicAdd(&s_fcnt[f], ws);
        }
        __syncthreads();
        // Finest level still holding >= 200 candidates
        float pivot = 0.98f;
        #pragma unroll
        for (int f = NFINE - 1; f >= 0; f--)
            if (s_fcnt[f] >= TOPK) pivot = FL[f];
        // Compact selected keys into the sort buffer
        #pragma unroll
        for (int r = 0; r < 3; r++) {
            float sc = __uint_as_float((unsigned int)(kreg[r] >> 32));
            if (sc > pivot) {
                int pos = atomicAdd(&s_num, 1);
                keys[pos] = kreg[r];
            }
        }
        __syncthreads();
        cnt = s_num;
    } else {
        // ---- Fallback (statistically never): full strided rescan with ladder.
        if (tid < NLAD) s_pcnt[tid] = 0;
        __syncthreads();
        const float PL[NLAD] = {0.9950f, 0.9925f, 0.9900f, 0.9875f, 0.9850f,
                                0.98f, 0.96f, 0.92f, 0.84f, 0.68f, 0.50f};
        const float* col = scores + (size_t)b * PERB + c;
        int lc[NLAD];
        #pragma unroll
        for (int l = 0; l < NLAD; l++) lc[l] = 0;
        for (int i = tid; i < ROWS; i += 256) {
            float v = col[(size_t)i * NCLS];
            #pragma unroll
            for (int l = 0; l < NLAD; l++) lc[l] += (v > PL[l]);
        }
        #pragma unroll
        for (int l = 0; l < NLAD; l++) {
            int ws = __reduce_add_sync(0xffffffffu, lc[l]);
            if (lane == 0 && ws) atomicAdd(&s_pcnt[l], ws);
        }
        __syncthreads();
        const int n05 = s_pcnt[NLAD - 1];
        const int target = (n05 < TOPK) ? n05 : TOPK;
        float pivot = 0.50f;
        #pragma unroll
        for (int l = NLAD - 1; l >= 0; l--)
            if (s_pcnt[l] >= target) pivot = PL[l];
        for (int i = tid; i < ROWS; i += 256) {
            float v = col[(size_t)i * NCLS];
            if (v > pivot) {
                int pos = atomicAdd(&s_num, 1);
                if (pos < CAP) keys[pos] = make_key(v, i);
            }
        }
        __syncthreads();
        cnt = s_num; if (cnt > CAP) cnt = CAP;
    }

    // ---- Sort descending. Typical path: register/shuffle bitonic on 256 keys
    //      (30 shfl steps, 6 smem steps). Fallback smem bitonic for cnt > 256.
    if (cnt <= 256) {
        for (int i = cnt + tid; i < 256; i += 256) keys[i] = 0ull;
        __syncthreads();
        unsigned long long key = keys[tid];
        #pragma unroll
        for (int k = 2; k <= 256; k <<= 1) {
            #pragma unroll
            for (int j = k >> 1; j > 0; j >>= 1) {
                unsigned long long other;
                if (j >= 32) {
                    keys[tid] = key;
                    __syncthreads();
                    other = keys[tid ^ j];
                    __syncthreads();
                } else {
                    other = __shfl_xor_sync(0xffffffffu, key, j);
                }
                bool keep_max = ((tid & k) == 0) == ((tid & j) == 0);
                key = ((key > other) == keep_max) ? key : other;
            }
        }
        keys[tid] = key;
        __syncthreads();
    } else {
        int P = 512; while (P < cnt) P <<= 1;
        for (int i = cnt + tid; i < P; i += 256) keys[i] = 0ull;
        __syncthreads();
        for (int k = 2; k <= P; k <<= 1) {
            for (int j = k >> 1; j > 0; j >>= 1) {
                for (int i = tid; i < P; i += 256) {
                    int l = i ^ j;
                    if (l > i) {
                        unsigned long long a = keys[i], d = keys[l];
                        bool sw = ((i & k) == 0) ? (a < d) : (a > d);
                        if (sw) { keys[i] = d; keys[l] = a; }
                    }
                }
                __syncthreads();
            }
        }
    }

    const int n_top = (cnt < TOPK) ? cnt : TOPK;

    // ---- Gather boxes for the top-200; also zero the padded sup array
    for (int k = tid; k < (TOPK + 1) * KW8 / 4; k += 256)
        ((uint4*)sup)[k] = make_uint4(0u, 0u, 0u, 0u);
    for (int k = tid; k < TOPK; k += 256) {
        if (k < n_top) {
            unsigned long long key = keys[k];
            int idx = (int)(~(unsigned int)(key & 0xffffffffull));
            float4 bb = ((const float4*)boxes)[(size_t)b * ROWS + idx];
            s_box4[k] = bb;
            s_area[k] = (bb.z - bb.x) * (bb.w - bb.y);
            s_sc[k]   = __uint_as_float((unsigned int)(key >> 32));
        } else {
            s_box4[k] = make_float4(0.f, 0.f, 0.f, 0.f);
            s_area[k] = 0.f; s_sc[k] = 0.f;
        }
    }
    __syncthreads();

    // ---- Suppression bitmask: one warp per row, ballot forms each 32-bit word.
    for (int r = wid; r < n_top; r += 8) {
        const float4 bi = s_box4[r];
        const float  ai = s_area[r];
        const int    w0 = r >> 5;
        for (int w = w0; w < KW; w++) {
            int j = w * 32 + lane;
            bool hit = false;
            if (j > r && j < n_top) {
                float4 bj = s_box4[j];
                float xx1 = fmaxf(bi.x, bj.x);
                float yy1 = fmaxf(bi.y, bj.y);
                float xx2 = fminf(bi.z, bj.z);
                float yy2 = fminf(bi.w, bj.w);
                float inter = fmaxf(0.f, xx2 - xx1) * fmaxf(0.f, yy2 - yy1);
                if (inter > 0.f) {
                    float un = (ai + s_area[j]) - inter;
                    hit = (inter / un) > 0.5f;
                }
            }
            unsigned int m = __ballot_sync(0xffffffffu, hit);
            if (lane == 0) sup[r * KW8 + w] = m;
        }
    }
    __syncthreads();

    // ---- Serial greedy on thread 0: rows as 2x uint4, prefetch row i+1.
    if (tid == 0) {
        const uint4* sv = (const uint4*)sup;
        unsigned int rem[KW8];
        #pragma unroll
        for (int w = 0; w < KW8; w++) rem[w] = 0u;
        uint4 n0 = sv[0], n1 = sv[1];
        #pragma unroll
        for (int w0 = 0; w0 < KW; w0++) {
            for (int ii = 0; ii < 32; ii++) {
                int idx = w0 * 32 + ii;
                if (idx >= n_top) break;
                uint4 c0 = n0, c1 = n1;
                n0 = sv[(idx + 1) * 2];
                n1 = sv[(idx + 1) * 2 + 1];
                if (((rem[w0] >> ii) & 1u) == 0u) {
                    rem[0] |= c0.x; rem[1] |= c0.y; rem[2] |= c0.z; rem[3] |= c0.w;
                    rem[4] |= c1.x; rem[5] |= c1.y; rem[6] |= c1.z;
                }
            }
        }
        #pragma unroll
        for (int w = 0; w < KW; w++) s_keepw[w] = ~rem[w];
        g_ccnt[bc] = 0;   // self-clean for next graph replay
    }
    __syncthreads();

    // ---- Write output: (b, c, k, 6) = [x1,y1,x2,y2,score,class] or zeros
    float* o = out + (size_t)bc * (TOPK * 6);
    const float cls = (float)c;
    for (int t = tid; t < TOPK * 6; t += 256) {
        int k = t / 6, f = t % 6;
        bool kp = (k < n_top) && (((s_keepw[k >> 5] >> (k & 31)) & 1u) != 0u);
        float v = 0.f;
        if (kp) {
            switch (f) {
                case 0: v = s_box4[k].x; break;
                case 1: v = s_box4[k].y; break;
                case 2: v = s_box4[k].z; break;
                case 3: v = s_box4[k].w; break;
                case 4: v = s_sc[k]; break;
                default: v = cls;   break;
            }
        }
        o[t] = v;
    }
}

// ---------------------------------------------------------------------------
extern "C" void kernel_launch(void* const* d_in, const int* in_sizes, int n_in,
                              void* d_out, int out_size) {
    const float* boxes  = (const float*)d_in[0];
    const float* scores = (const float*)d_in[1];
    if (n_in >= 2 && in_sizes[0] > in_sizes[1]) {  // scores is the bigger tensor
        boxes  = (const float*)d_in[1];
        scores = (const float*)d_in[0];
    }
    float* out = (float*)d_out;

    scatter_kernel<<<SCAT_BLK, 256>>>((const float4*)scores);
    nms_kernel<<<NBC, 256>>>(boxes, scores, out);
}